// round 1
// baseline (speedup 1.0000x reference)
#include <cuda_runtime.h>
#include <math.h>

// Problem constants (fixed shapes)
#define BB   4
#define SS   2048
#define GG   8
#define DD   128
#define NNs  64
#define BGc  (BB*GG)            // 32
#define NCHUNK 8
#define CSZ  256
#define NTOK (BB*SS*GG)         // 65536

// Scratch (device globals; no allocation allowed)
__device__ float4 g_ab[BGc*SS*NNs];        // (a_r, a_i, bx_r, bx_i) 64 MB
__device__ float2 g_h[BGc*SS*NNs];         // scanned states, 32 MB
__device__ float2 g_P[BGc*NCHUNK*NNs];     // chunk transition products
__device__ float2 g_hend[BGc*NCHUNK*NNs];  // chunk local end-states
__device__ float2 g_hin[BGc*NCHUNK*NNs];   // chunk input states

// ---------------------------------------------------------------------------
// Kernel 1: per-token dt, A=(a_r,a_i), Bx=(bx_r,bx_i). 64 tokens per block.
// smem: bw[d][n] float2 with XOR swizzle (conflict-free fill + read),
//       dt_w, neg_softplus(log_A_mag), A_phase, per-warp x buffers.
// ---------------------------------------------------------------------------
__global__ __launch_bounds__(256) void k1_proj(
    const float* __restrict__ xr_g, const float* __restrict__ xi_g,
    const float* __restrict__ logA, const float* __restrict__ Aph_g,
    const float* __restrict__ Bwr,  const float* __restrict__ Bwi,
    const float* __restrict__ dtw_g, const float* __restrict__ dtb_g)
{
    extern __shared__ float sm[];
    float2* bw  = (float2*)sm;            // 8192 float2 (64 KB)
    float*  dtw = sm + 8192*2;            // 512
    float*  nlA = dtw + 512;              // 512
    float*  aph = nlA + 512;              // 512
    float*  xb  = aph + 512;              // 8 warps * 512

    const int tid = threadIdx.x;

    // Fill Bw transposed+swizzled: bw[d*64 + (n ^ (d&31))] = (Bwr[n][d], Bwi[n][d])
    for (int i = tid; i < NNs*DD; i += 256) {
        int n = i >> 7, d = i & 127;
        bw[d*64 + (n ^ (d & 31))] = make_float2(Bwr[i], Bwi[i]);
    }
    for (int i = tid; i < 512; i += 256) {
        dtw[i] = dtw_g[i];
        nlA[i] = -log1pf(expf(logA[i]));   // -softplus(log_A_mag)
        aph[i] = Aph_g[i];
    }
    __syncthreads();

    const int w = tid >> 5, l = tid & 31;
    float* xb0 = xb + w*512;
    float* xb1 = xb0 + 256;
    const float db0 = dtb_g[0], db1 = dtb_g[1];
    const int base = blockIdx.x*64 + w*8;

    for (int it = 0; it < 4; ++it) {
        int t0 = base + it*2, t1 = t0 + 1;

        // cooperative x load: xb[0..127]=x_r, xb[128..255]=x_i
        ((float4*)xb0)[l]      = ((const float4*)(xr_g + (size_t)t0*128))[l];
        ((float4*)xb0)[l + 32] = ((const float4*)(xi_g + (size_t)t0*128))[l];
        ((float4*)xb1)[l]      = ((const float4*)(xr_g + (size_t)t1*128))[l];
        ((float4*)xb1)[l + 32] = ((const float4*)(xi_g + (size_t)t1*128))[l];
        __syncwarp();

        // dt logits: two dots of length 256 per token
        float p00=0.f, p01=0.f, p10=0.f, p11=0.f;
        #pragma unroll
        for (int k = 0; k < 8; ++k) {
            int d = l + 32*k;
            float w0 = dtw[d], w1 = dtw[256 + d];
            float a0 = xb0[d], a1 = xb1[d];
            p00 = fmaf(a0, w0, p00); p01 = fmaf(a0, w1, p01);
            p10 = fmaf(a1, w0, p10); p11 = fmaf(a1, w1, p11);
        }
        #pragma unroll
        for (int off = 16; off; off >>= 1) {
            p00 += __shfl_xor_sync(0xffffffffu, p00, off);
            p01 += __shfl_xor_sync(0xffffffffu, p01, off);
            p10 += __shfl_xor_sync(0xffffffffu, p10, off);
            p11 += __shfl_xor_sync(0xffffffffu, p11, off);
        }
        float dtm0 = fminf(fmaxf(expf(p00 + db0), 1e-4f), 2.0f);
        float dtp0 = fminf(fmaxf(expf(p01 + db1), 1e-4f), 2.0f);
        float dtm1 = fminf(fmaxf(expf(p10 + db0), 1e-4f), 2.0f);
        float dtp1 = fminf(fmaxf(expf(p11 + db1), 1e-4f), 2.0f);

        // complex B projection: lane handles n0=l, n1=l+32, two tokens
        float a0r=0,a0i=0,a1r=0,a1i=0, b0r=0,b0i=0,b1r=0,b1i=0;
        #pragma unroll 4
        for (int d = 0; d < 128; ++d) {
            int swi = d*64 + (l ^ (d & 31));
            float2 w0 = bw[swi];
            float2 w1 = bw[swi + 32];
            float xr0 = xb0[d], xi0 = xb0[128 + d];
            float xr1 = xb1[d], xi1 = xb1[128 + d];
            a0r = fmaf(xr0, w0.x, fmaf(-xi0, w0.y, a0r));
            a0i = fmaf(xr0, w0.y, fmaf( xi0, w0.x, a0i));
            a1r = fmaf(xr0, w1.x, fmaf(-xi0, w1.y, a1r));
            a1i = fmaf(xr0, w1.y, fmaf( xi0, w1.x, a1i));
            b0r = fmaf(xr1, w0.x, fmaf(-xi1, w0.y, b0r));
            b0i = fmaf(xr1, w0.y, fmaf( xi1, w0.x, b0i));
            b1r = fmaf(xr1, w1.x, fmaf(-xi1, w1.y, b1r));
            b1i = fmaf(xr1, w1.y, fmaf( xi1, w1.x, b1i));
        }

        // A and store, token 0
        {
            int b = t0 >> 14, rem = t0 & 16383, s = rem >> 3, g = rem & 7;
            int gb = g*64;
            size_t idx = ((size_t)(b*GG + g)*SS + s)*NNs;
            float si, co;
            float am = expf(dtm0 * nlA[gb + l]);
            sincosf(dtp0 * aph[gb + l], &si, &co);
            g_ab[idx + l] = make_float4(am*co, am*si, a0r*dtm0, a0i*dtm0);
            am = expf(dtm0 * nlA[gb + l + 32]);
            sincosf(dtp0 * aph[gb + l + 32], &si, &co);
            g_ab[idx + l + 32] = make_float4(am*co, am*si, a1r*dtm0, a1i*dtm0);
        }
        // token 1
        {
            int b = t1 >> 14, rem = t1 & 16383, s = rem >> 3, g = rem & 7;
            int gb = g*64;
            size_t idx = ((size_t)(b*GG + g)*SS + s)*NNs;
            float si, co;
            float am = expf(dtm1 * nlA[gb + l]);
            sincosf(dtp1 * aph[gb + l], &si, &co);
            g_ab[idx + l] = make_float4(am*co, am*si, b0r*dtm1, b0i*dtm1);
            am = expf(dtm1 * nlA[gb + l + 32]);
            sincosf(dtp1 * aph[gb + l + 32], &si, &co);
            g_ab[idx + l + 32] = make_float4(am*co, am*si, b1r*dtm1, b1i*dtm1);
        }
        __syncwarp();
    }
}

// ---------------------------------------------------------------------------
// Kernel 2a: per-chunk local scan (h0=0) + chunk transition product
// ---------------------------------------------------------------------------
__global__ __launch_bounds__(64) void k2a_chunk(void)
{
    int blk = blockIdx.x;              // 0..255
    int bg = blk >> 3, c = blk & 7;
    int n = threadIdx.x;
    size_t base = ((size_t)bg*SS + c*CSZ)*NNs + n;

    float hr=0.f, hi=0.f, pr=1.f, pi=0.f;
    float4 buf[8];
    #pragma unroll
    for (int j = 0; j < 8; ++j) buf[j] = g_ab[base + (size_t)j*NNs];

    for (int t0 = 0; t0 < CSZ; t0 += 8) {
        #pragma unroll
        for (int j = 0; j < 8; ++j) {
            float4 a = buf[j];
            int tn = t0 + 8 + j;
            if (tn < CSZ) buf[j] = g_ab[base + (size_t)tn*NNs];
            float nr = fmaf(a.x, hr, fmaf(-a.y, hi, a.z));
            float ni = fmaf(a.x, hi, fmaf( a.y, hr, a.w));
            hr = nr; hi = ni;
            float qr = a.x*pr - a.y*pi;
            float qi = a.x*pi + a.y*pr;
            pr = qr; pi = qi;
        }
    }
    int o = (bg*NCHUNK + c)*NNs + n;
    g_P[o]    = make_float2(pr, pi);
    g_hend[o] = make_float2(hr, hi);
}

// ---------------------------------------------------------------------------
// Kernel 2b: sequential chunk combine (tiny) — renorm at chunk boundaries
// ---------------------------------------------------------------------------
__global__ __launch_bounds__(64) void k2b_combine(void)
{
    int bg = blockIdx.x;
    int n = threadIdx.x;
    float hr = 0.f, hi = 0.f;
    for (int c = 0; c < NCHUNK; ++c) {
        int o = (bg*NCHUNK + c)*NNs + n;
        g_hin[o] = make_float2(hr, hi);
        float2 P = g_P[o], he = g_hend[o];
        float nr = fmaf(P.x, hr, fmaf(-P.y, hi, he.x));
        float ni = fmaf(P.x, hi, fmaf( P.y, hr, he.y));
        float nrm = sqrtf(nr*nr + ni*ni + 1e-8f);
        float sc = fminf(nrm, 100.0f) / nrm;
        hr = nr*sc; hi = ni*sc;
    }
}

// ---------------------------------------------------------------------------
// Kernel 2c: rescan each chunk from its true h_in, write all states
// ---------------------------------------------------------------------------
__global__ __launch_bounds__(64) void k2c_rescan(void)
{
    int blk = blockIdx.x;
    int bg = blk >> 3, c = blk & 7;
    int n = threadIdx.x;
    size_t base = ((size_t)bg*SS + c*CSZ)*NNs + n;

    float2 h0 = g_hin[(bg*NCHUNK + c)*NNs + n];
    float hr = h0.x, hi = h0.y;

    float4 buf[8];
    #pragma unroll
    for (int j = 0; j < 8; ++j) buf[j] = g_ab[base + (size_t)j*NNs];

    for (int t0 = 0; t0 < CSZ; t0 += 8) {
        #pragma unroll
        for (int j = 0; j < 8; ++j) {
            float4 a = buf[j];
            int t = t0 + j;
            int tn = t + 8;
            if (tn < CSZ) buf[j] = g_ab[base + (size_t)tn*NNs];
            float nr = fmaf(a.x, hr, fmaf(-a.y, hi, a.z));
            float ni = fmaf(a.x, hi, fmaf( a.y, hr, a.w));
            if (t == CSZ - 1) {
                float nrm = sqrtf(nr*nr + ni*ni + 1e-8f);
                float sc = fminf(nrm, 100.0f) / nrm;
                nr *= sc; ni *= sc;
            }
            hr = nr; hi = ni;
            g_h[base + (size_t)t*NNs] = make_float2(hr, hi);
        }
    }
}

// ---------------------------------------------------------------------------
// Kernel 3: y = C-projection of h. 64 tokens per block, 2 tokens per warp.
// ---------------------------------------------------------------------------
__global__ __launch_bounds__(256) void k3_out(
    const float* __restrict__ Cwr, const float* __restrict__ Cwi,
    float* __restrict__ out)
{
    extern __shared__ float sm[];
    float2* cw = (float2*)sm;                 // 8192 float2 (64 KB)
    float2* hb = (float2*)(sm + 8192*2);      // 8 warps * 128 float2

    const int tid = threadIdx.x;
    // cw[n*128 + (d ^ (n&31))] = (Cw_r[d][n], Cw_i[d][n])
    for (int i = tid; i < DD*NNs; i += 256) {
        int d = i >> 6, n = i & 63;
        cw[n*128 + (d ^ (n & 31))] = make_float2(Cwr[i], Cwi[i]);
    }
    __syncthreads();

    const int w = tid >> 5, l = tid & 31;
    float2* hb0 = hb + w*128;
    float2* hb1 = hb0 + 64;
    const int base = blockIdx.x*64 + w*8;
    const size_t BSGD = (size_t)NTOK*DD;

    for (int it = 0; it < 4; ++it) {
        int t0 = base + it*2, t1 = t0 + 1;
        // h scratch index per token
        int b0 = t0 >> 14, r0 = t0 & 16383;
        int b1 = t1 >> 14, r1 = t1 & 16383;
        size_t hg0 = ((size_t)(b0*GG + (r0 & 7))*SS + (r0 >> 3))*NNs;
        size_t hg1 = ((size_t)(b1*GG + (r1 & 7))*SS + (r1 >> 3))*NNs;
        hb0[l] = g_h[hg0 + l]; hb0[l + 32] = g_h[hg0 + l + 32];
        hb1[l] = g_h[hg1 + l]; hb1[l + 32] = g_h[hg1 + l + 32];
        __syncwarp();

        float acc[16];
        #pragma unroll
        for (int i = 0; i < 16; ++i) acc[i] = 0.f;

        #pragma unroll 4
        for (int n = 0; n < 64; ++n) {
            float2 h0 = hb0[n], h1 = hb1[n];
            int swb = n*128 + (l ^ (n & 31));
            #pragma unroll
            for (int k = 0; k < 4; ++k) {
                float2 c = cw[swb + 32*k];
                int a = k*2;
                acc[a]     = fmaf(h0.x, c.x, fmaf(-h0.y, c.y, acc[a]));
                acc[a + 1] = fmaf(h0.x, c.y, fmaf( h0.y, c.x, acc[a + 1]));
                acc[a + 8] = fmaf(h1.x, c.x, fmaf(-h1.y, c.y, acc[a + 8]));
                acc[a + 9] = fmaf(h1.x, c.y, fmaf( h1.y, c.x, acc[a + 9]));
            }
        }
        #pragma unroll
        for (int k = 0; k < 4; ++k) {
            out[(size_t)t0*DD + l + 32*k]        = acc[k*2];
            out[BSGD + (size_t)t0*DD + l + 32*k] = acc[k*2 + 1];
            out[(size_t)t1*DD + l + 32*k]        = acc[k*2 + 8];
            out[BSGD + (size_t)t1*DD + l + 32*k] = acc[k*2 + 9];
        }
        __syncwarp();
    }
}

// ---------------------------------------------------------------------------
extern "C" void kernel_launch(void* const* d_in, const int* in_sizes, int n_in,
                              void* d_out, int out_size)
{
    const float* x_r   = (const float*)d_in[0];
    const float* x_i   = (const float*)d_in[1];
    const float* logA  = (const float*)d_in[2];
    const float* Aph   = (const float*)d_in[3];
    const float* Bwr   = (const float*)d_in[4];
    const float* Bwi   = (const float*)d_in[5];
    const float* Cwr   = (const float*)d_in[6];
    const float* Cwi   = (const float*)d_in[7];
    const float* dtw   = (const float*)d_in[8];
    const float* dtb   = (const float*)d_in[9];
    float* out = (float*)d_out;

    const int smem1 = (8192*2 + 512*3 + 8*512) * 4;   // 88064 B
    const int smem3 = (8192*2 + 8*128*2) * 4;         // 73728 B
    cudaFuncSetAttribute(k1_proj, cudaFuncAttributeMaxDynamicSharedMemorySize, smem1);
    cudaFuncSetAttribute(k3_out,  cudaFuncAttributeMaxDynamicSharedMemorySize, smem3);

    k1_proj<<<NTOK/64, 256, smem1>>>(x_r, x_i, logA, Aph, Bwr, Bwi, dtw, dtb);
    k2a_chunk<<<BGc*NCHUNK, 64>>>();
    k2b_combine<<<BGc, 64>>>();
    k2c_rescan<<<BGc*NCHUNK, 64>>>();
    k3_out<<<NTOK/64, 256, smem3>>>(Cwr, Cwi, out);
}

// round 2
// speedup vs baseline: 1.1006x; 1.1006x over previous
#include <cuda_runtime.h>
#include <math.h>
#include <stdint.h>

// Fixed problem shapes
#define BB   4
#define SS   2048
#define GG   8
#define DD   128
#define NN   64
#define BG   (BB*GG)          // 32
#define NTOK (BB*SS*GG)       // 65536
#define SUB  32
#define NSUB (SS/SUB)         // 64
#define NGRP (NTOK/64)        // 1024 token-groups of 64
#define GRID_PERS 148

typedef unsigned long long ull;

// Scratch (device globals; no allocation allowed)
__device__ float4 g_ab[BG*SS*NN];          // (a_r, a_i, bx_r, bx_i)   64 MB
__device__ float4 g_hc[BG*SS*NN];          // (hl_r, hl_i, c_r, c_i)   64 MB
__device__ float2 g_hin[BG*NSUB*NN];       // subchunk input states     1 MB

// ---------------- f32x2 helpers ----------------
__device__ __forceinline__ ull pk(float x, float y) {
    ull r; asm("mov.b64 %0, {%1, %2};" : "=l"(r) : "f"(x), "f"(y)); return r;
}
__device__ __forceinline__ void upk(ull v, float& x, float& y) {
    asm("mov.b64 {%0, %1}, %2;" : "=f"(x), "=f"(y) : "l"(v));
}
__device__ __forceinline__ void fma2(ull& d, ull a, ull b) {
    asm("fma.rn.f32x2 %0, %1, %2, %0;" : "+l"(d) : "l"(a), "l"(b));
}
__device__ __forceinline__ ull neg2(ull v) { return v ^ 0x8000000080000000ULL; }
__device__ __forceinline__ float comp(ull v, int e) {
    float x, y; upk(v, x, y); return e ? y : x;
}
__device__ __forceinline__ float warpsum(float v) {
    #pragma unroll
    for (int off = 16; off; off >>= 1) v += __shfl_xor_sync(0xffffffffu, v, off);
    return v;
}

// ---------------------------------------------------------------------------
// Kernel 1: per-token dt, A, Bx.  Persistent blocks; 8 warps x 8 tokens/group.
// Weights pre-duplicated in smem as (w,w) pairs; x staged as token-pair
// interleaved float2; inner loop = pure FFMA2.
// ---------------------------------------------------------------------------
__global__ __launch_bounds__(256, 1) void k1_proj(
    const float* __restrict__ xr_g, const float* __restrict__ xi_g,
    const float* __restrict__ logA, const float* __restrict__ Aph_g,
    const float* __restrict__ Bwr,  const float* __restrict__ Bwi,
    const float* __restrict__ dtw_g, const float* __restrict__ dtb_g)
{
    extern __shared__ float sm[];
    float2* wrr = (float2*)sm;            // [DD][NN] (wr,wr)   64 KB
    float2* wii = wrr + DD*NN;            // [DD][NN] (wi,wi)   64 KB
    float*  dtw = (float*)(wii + DD*NN);  // 512
    float*  nlA = dtw + 512;              // 512
    float*  aph = nlA + 512;              // 512
    float2* xbase = (float2*)(aph + 512); // 8 warps * 1024 float2 (64 KB)

    const int tid = threadIdx.x;

    // one-time per block: fill duplicated weights (STS conflict-free)
    for (int i = tid; i < NN*DD; i += 256) {
        int n = i & 63, d = i >> 6;
        float wr = Bwr[n*DD + d], wi = Bwi[n*DD + d];
        wrr[d*NN + n] = make_float2(wr, wr);
        wii[d*NN + n] = make_float2(wi, wi);
    }
    for (int i = tid; i < 512; i += 256) {
        dtw[i] = dtw_g[i];
        nlA[i] = -log1pf(expf(logA[i]));
        aph[i] = Aph_g[i];
    }
    __syncthreads();

    const int w = tid >> 5, l = tid & 31;
    float2* xpr = xbase + w*(8*DD);       // 4 pairs x 128 d, xr pairs
    float2* xpi = xpr + 4*DD;             // xi pairs
    const float db0 = dtb_g[0], db1 = dtb_g[1];

    for (int grp = blockIdx.x; grp < NGRP; grp += gridDim.x) {
        const int tbase = grp*64 + w*8;

        // ---- stage x as token-pair interleaved float2 ----
        #pragma unroll
        for (int p = 0; p < 4; ++p) {
            int t0 = tbase + 2*p, t1 = t0 + 1;
            float4 r0 = ((const float4*)(xr_g + (size_t)t0*DD))[l];
            float4 r1 = ((const float4*)(xr_g + (size_t)t1*DD))[l];
            float4 i0 = ((const float4*)(xi_g + (size_t)t0*DD))[l];
            float4 i1 = ((const float4*)(xi_g + (size_t)t1*DD))[l];
            float2* xp = xpr + p*DD;
            *(float4*)&xp[4*l]     = make_float4(r0.x, r1.x, r0.y, r1.y);
            *(float4*)&xp[4*l + 2] = make_float4(r0.z, r1.z, r0.w, r1.w);
            float2* xq = xpi + p*DD;
            *(float4*)&xq[4*l]     = make_float4(i0.x, i1.x, i0.y, i1.y);
            *(float4*)&xq[4*l + 2] = make_float4(i0.z, i1.z, i0.w, i1.w);
        }
        __syncwarp();

        // ---- dt logits (small) ----
        float dm[8], dp[8];
        #pragma unroll
        for (int p = 0; p < 4; ++p) {
            float2 a0 = make_float2(0.f, 0.f), a1 = make_float2(0.f, 0.f);
            #pragma unroll
            for (int k = 0; k < 4; ++k) {
                int d = l + 32*k;
                float2 xr = xpr[p*DD + d];
                float2 xi = xpi[p*DD + d];
                float w0r = dtw[d], w0i = dtw[128 + d];
                float w1r = dtw[256 + d], w1i = dtw[384 + d];
                a0.x = fmaf(xr.x, w0r, fmaf(xi.x, w0i, a0.x));
                a0.y = fmaf(xr.y, w0r, fmaf(xi.y, w0i, a0.y));
                a1.x = fmaf(xr.x, w1r, fmaf(xi.x, w1i, a1.x));
                a1.y = fmaf(xr.y, w1r, fmaf(xi.y, w1i, a1.y));
            }
            a0.x = warpsum(a0.x); a0.y = warpsum(a0.y);
            a1.x = warpsum(a1.x); a1.y = warpsum(a1.y);
            dm[2*p]   = fminf(fmaxf(__expf(a0.x + db0), 1e-4f), 2.0f);
            dm[2*p+1] = fminf(fmaxf(__expf(a0.y + db0), 1e-4f), 2.0f);
            dp[2*p]   = fminf(fmaxf(__expf(a1.x + db1), 1e-4f), 2.0f);
            dp[2*p+1] = fminf(fmaxf(__expf(a1.y + db1), 1e-4f), 2.0f);
        }

        // ---- main complex B projection: FFMA2 ----
        ull aR[4][2], aI[4][2];
        #pragma unroll
        for (int p = 0; p < 4; ++p) { aR[p][0]=0; aR[p][1]=0; aI[p][0]=0; aI[p][1]=0; }

        for (int d = 0; d < DD; d += 2) {
            const float2* wd = wrr + d*NN;
            const float2* vd = wii + d*NN;
            ull wr0a = *(const ull*)&wd[l];
            ull wr1a = *(const ull*)&wd[l+32];
            ull wr0b = *(const ull*)&wd[NN + l];
            ull wr1b = *(const ull*)&wd[NN + l+32];
            ull wi0a = *(const ull*)&vd[l];
            ull wi1a = *(const ull*)&vd[l+32];
            ull wi0b = *(const ull*)&vd[NN + l];
            ull wi1b = *(const ull*)&vd[NN + l+32];
            ull ni0a = neg2(wi0a), ni1a = neg2(wi1a);
            ull ni0b = neg2(wi0b), ni1b = neg2(wi1b);
            #pragma unroll
            for (int p = 0; p < 4; ++p) {
                float4 xr4 = *(const float4*)(xpr + p*DD + d);
                float4 xi4 = *(const float4*)(xpi + p*DD + d);
                ull xra = pk(xr4.x, xr4.y), xrb = pk(xr4.z, xr4.w);
                ull xia = pk(xi4.x, xi4.y), xib = pk(xi4.z, xi4.w);
                fma2(aR[p][0], xra, wr0a); fma2(aR[p][0], xia, ni0a);
                fma2(aI[p][0], xra, wi0a); fma2(aI[p][0], xia, wr0a);
                fma2(aR[p][1], xra, wr1a); fma2(aR[p][1], xia, ni1a);
                fma2(aI[p][1], xra, wi1a); fma2(aI[p][1], xia, wr1a);
                fma2(aR[p][0], xrb, wr0b); fma2(aR[p][0], xib, ni0b);
                fma2(aI[p][0], xrb, wi0b); fma2(aI[p][0], xib, wr0b);
                fma2(aR[p][1], xrb, wr1b); fma2(aR[p][1], xib, ni1b);
                fma2(aI[p][1], xrb, wi1b); fma2(aI[p][1], xib, wr1b);
            }
        }

        // ---- epilogue: A (exp/sincos) + scaled Bx, write float4 ----
        #pragma unroll
        for (int p = 0; p < 4; ++p) {
            #pragma unroll
            for (int e = 0; e < 2; ++e) {
                int t = tbase + 2*p + e;
                float dmv = dm[2*p + e], dpv = dp[2*p + e];
                int b = t >> 14, g = t & 7, s = (t >> 3) & 2047;
                size_t idx = ((size_t)(b*GG + g)*SS + s)*NN;
                #pragma unroll
                for (int ns = 0; ns < 2; ++ns) {
                    int n = l + 32*ns;
                    float br = comp(aR[p][ns], e) * dmv;
                    float bi = comp(aI[p][ns], e) * dmv;
                    float am = __expf(dmv * nlA[g*64 + n]);
                    float sn, cs;
                    __sincosf(dpv * aph[g*64 + n], &sn, &cs);
                    g_ab[idx + n] = make_float4(am*cs, am*sn, br, bi);
                }
            }
        }
        __syncwarp();
    }
}

// ---------------------------------------------------------------------------
// Kernel 2a: per-subchunk (32 tokens) local scan from 0; store (h_local, c).
// ---------------------------------------------------------------------------
__global__ __launch_bounds__(64) void k2a_sub(void)
{
    int blk = blockIdx.x;                 // 0..2047
    int bg = blk >> 6, sub = blk & 63;
    int n = threadIdx.x;
    size_t base = ((size_t)bg*SS + sub*SUB)*NN + n;

    float hr = 0.f, hi = 0.f, cr = 1.f, ci = 0.f;
    float4 buf[8];
    #pragma unroll
    for (int j = 0; j < 8; ++j) buf[j] = g_ab[base + (size_t)j*NN];

    #pragma unroll
    for (int t0 = 0; t0 < SUB; t0 += 8) {
        #pragma unroll
        for (int j = 0; j < 8; ++j) {
            float4 a = buf[j];
            int tn = t0 + 8 + j;
            if (tn < SUB) buf[j] = g_ab[base + (size_t)tn*NN];
            float nr = fmaf(a.x, hr, fmaf(-a.y, hi, a.z));
            float ni = fmaf(a.x, hi, fmaf( a.y, hr, a.w));
            hr = nr; hi = ni;
            float qr = a.x*cr - a.y*ci;
            float qi = a.x*ci + a.y*cr;
            cr = qr; ci = qi;
            g_hc[base + (size_t)(t0 + j)*NN] = make_float4(hr, hi, cr, ci);
        }
    }
}

// ---------------------------------------------------------------------------
// Kernel 2b: sequential subchunk combine; renorm every 8th subchunk boundary.
// ---------------------------------------------------------------------------
__global__ __launch_bounds__(64) void k2b_combine(void)
{
    int bg = blockIdx.x;
    int n = threadIdx.x;
    float hr = 0.f, hi = 0.f;

    float4 ebuf[8];
    #pragma unroll
    for (int j = 0; j < 8; ++j)
        ebuf[j] = g_hc[((size_t)bg*SS + j*SUB + 31)*NN + n];

    for (int s0 = 0; s0 < NSUB; s0 += 8) {
        #pragma unroll
        for (int j = 0; j < 8; ++j) {
            float4 e = ebuf[j];
            int nsub = s0 + 8 + j;
            if (nsub < NSUB)
                ebuf[j] = g_hc[((size_t)bg*SS + nsub*SUB + 31)*NN + n];
            int sub = s0 + j;
            g_hin[(bg*NSUB + sub)*NN + n] = make_float2(hr, hi);
            float nr = fmaf(e.z, hr, fmaf(-e.w, hi, e.x));
            float ni = fmaf(e.z, hi, fmaf( e.w, hr, e.y));
            if ((sub & 7) == 7) {
                float nm = sqrtf(nr*nr + ni*ni + 1e-8f);
                float sc = fminf(nm, 100.0f)/nm;
                nr *= sc; ni *= sc;
            }
            hr = nr; hi = ni;
        }
    }
}

// ---------------------------------------------------------------------------
// Kernel 3: correction h = h_local + c*h_in (+renorm at s%256==255) fused with
// the complex C projection, FFMA2 token-pair packed. Persistent blocks.
// ---------------------------------------------------------------------------
__global__ __launch_bounds__(256, 1) void k3_out(
    const float* __restrict__ Cwr, const float* __restrict__ Cwi,
    float* __restrict__ out)
{
    extern __shared__ float sm[];
    float2* crr = (float2*)sm;            // [NN][DD] (cr,cr)   64 KB
    float2* cii = crr + NN*DD;            // [NN][DD] (ci,ci)   64 KB
    float*  hbase = (float*)(cii + NN*DD);// 8 warps * 1536 floats (48 KB)

    const int tid = threadIdx.x;
    for (int i = tid; i < DD*NN; i += 256) {
        int d = i & 127, n = i >> 7;
        float cr = Cwr[d*NN + n], ci = Cwi[d*NN + n];
        crr[n*DD + d] = make_float2(cr, cr);
        cii[n*DD + d] = make_float2(ci, ci);
    }
    __syncthreads();

    const int w = tid >> 5, l = tid & 31;
    float* hrp = hbase + w*1536;          // [4 pairs][64 n][2 parity]
    float* hip = hrp + 512;
    float* hnp = hip + 512;
    const size_t OFF = (size_t)NTOK*DD;

    for (int grp = blockIdx.x; grp < NGRP; grp += gridDim.x) {
        const int tbase = grp*64 + w*8;

        // ---- stage corrected h into token-pair interleaved smem ----
        #pragma unroll
        for (int k = 0; k < 8; ++k) {
            int t = tbase + k;
            int b = t >> 14, g = t & 7, s = (t >> 3) & 2047;
            int bg = b*GG + g;
            size_t idx = ((size_t)bg*SS + s)*NN;
            int hini = (bg*NSUB + (s >> 5))*NN;
            int p = k >> 1, e = k & 1;
            #pragma unroll
            for (int ns = 0; ns < 2; ++ns) {
                int n = l + 32*ns;
                float4 hc = g_hc[idx + n];
                float2 hin = g_hin[hini + n];
                float hr = fmaf(hc.z, hin.x, fmaf(-hc.w, hin.y, hc.x));
                float hi = fmaf(hc.z, hin.y, fmaf( hc.w, hin.x, hc.y));
                if ((s & 255) == 255) {
                    float nm = sqrtf(hr*hr + hi*hi + 1e-8f);
                    float sc = fminf(nm, 100.0f)/nm;
                    hr *= sc; hi *= sc;
                }
                hrp[(p*64 + n)*2 + e] = hr;
                hip[(p*64 + n)*2 + e] = hi;
                hnp[(p*64 + n)*2 + e] = -hi;
            }
        }
        __syncwarp();

        // ---- FFMA2 C projection: lane owns d = {2l,2l+1,2l+64,2l+65} ----
        ull aR[4][4], aI[4][4];   // [dslot][pair]
        #pragma unroll
        for (int i = 0; i < 4; ++i)
            #pragma unroll
            for (int p = 0; p < 4; ++p) { aR[i][p] = 0; aI[i][p] = 0; }

        for (int n = 0; n < NN; ++n) {
            float4 w0 = *(const float4*)&crr[n*DD + 2*l];        // d=2l,2l+1
            float4 w1 = *(const float4*)&crr[n*DD + 2*l + 64];   // d=2l+64,+65
            float4 v0 = *(const float4*)&cii[n*DD + 2*l];
            float4 v1 = *(const float4*)&cii[n*DD + 2*l + 64];
            ull cr0 = pk(w0.x, w0.y), cr1 = pk(w0.z, w0.w);
            ull cr2 = pk(w1.x, w1.y), cr3 = pk(w1.z, w1.w);
            ull ci0 = pk(v0.x, v0.y), ci1 = pk(v0.z, v0.w);
            ull ci2 = pk(v1.x, v1.y), ci3 = pk(v1.z, v1.w);
            #pragma unroll
            for (int p = 0; p < 4; ++p) {
                ull hr = *(const ull*)&hrp[(p*64 + n)*2];
                ull hi = *(const ull*)&hip[(p*64 + n)*2];
                ull hn = *(const ull*)&hnp[(p*64 + n)*2];
                fma2(aR[0][p], hr, cr0); fma2(aR[0][p], hn, ci0);
                fma2(aI[0][p], hr, ci0); fma2(aI[0][p], hi, cr0);
                fma2(aR[1][p], hr, cr1); fma2(aR[1][p], hn, ci1);
                fma2(aI[1][p], hr, ci1); fma2(aI[1][p], hi, cr1);
                fma2(aR[2][p], hr, cr2); fma2(aR[2][p], hn, ci2);
                fma2(aI[2][p], hr, ci2); fma2(aI[2][p], hi, cr2);
                fma2(aR[3][p], hr, cr3); fma2(aR[3][p], hn, ci3);
                fma2(aI[3][p], hr, ci3); fma2(aI[3][p], hi, cr3);
            }
        }

        // ---- output ----
        #pragma unroll
        for (int k = 0; k < 8; ++k) {
            int t = tbase + k;
            int p = k >> 1, e = k & 1;
            float r0 = comp(aR[0][p], e), r1 = comp(aR[1][p], e);
            float r2 = comp(aR[2][p], e), r3 = comp(aR[3][p], e);
            float i0 = comp(aI[0][p], e), i1 = comp(aI[1][p], e);
            float i2 = comp(aI[2][p], e), i3 = comp(aI[3][p], e);
            *(float2*)&out[(size_t)t*DD + 2*l]            = make_float2(r0, r1);
            *(float2*)&out[(size_t)t*DD + 2*l + 64]       = make_float2(r2, r3);
            *(float2*)&out[OFF + (size_t)t*DD + 2*l]      = make_float2(i0, i1);
            *(float2*)&out[OFF + (size_t)t*DD + 2*l + 64] = make_float2(i2, i3);
        }
        __syncwarp();
    }
}

// ---------------------------------------------------------------------------
extern "C" void kernel_launch(void* const* d_in, const int* in_sizes, int n_in,
                              void* d_out, int out_size)
{
    const float* x_r  = (const float*)d_in[0];
    const float* x_i  = (const float*)d_in[1];
    const float* logA = (const float*)d_in[2];
    const float* Aph  = (const float*)d_in[3];
    const float* Bwr  = (const float*)d_in[4];
    const float* Bwi  = (const float*)d_in[5];
    const float* Cwr  = (const float*)d_in[6];
    const float* Cwi  = (const float*)d_in[7];
    const float* dtw  = (const float*)d_in[8];
    const float* dtb  = (const float*)d_in[9];
    float* out = (float*)d_out;

    const int smem1 = (DD*NN*2*2 + 512*3 + 8*8*DD*2) * 4;   // 202752 B
    const int smem3 = (NN*DD*2*2 + 8*1536) * 4;             // 180224 B
    cudaFuncSetAttribute(k1_proj, cudaFuncAttributeMaxDynamicSharedMemorySize, smem1);
    cudaFuncSetAttribute(k3_out,  cudaFuncAttributeMaxDynamicSharedMemorySize, smem3);

    k1_proj<<<GRID_PERS, 256, smem1>>>(x_r, x_i, logA, Aph, Bwr, Bwi, dtw, dtb);
    k2a_sub<<<BG*NSUB, 64>>>();
    k2b_combine<<<BG, 64>>>();
    k3_out<<<GRID_PERS, 256, smem3>>>(Cwr, Cwi, out);
}

// round 3
// speedup vs baseline: 1.2344x; 1.1216x over previous
#include <cuda_runtime.h>
#include <math.h>
#include <stdint.h>

// Fixed problem shapes
#define BB   4
#define SS   2048
#define GG   8
#define DD   128
#define NN   64
#define BG   (BB*GG)          // 32
#define NTOK (BB*SS*GG)       // 65536
#define SUB  32
#define NSUB (SS/SUB)         // 64

typedef unsigned long long ull;

// Scratch (device globals; no allocation allowed)
__device__ float4 g_hc[BG*SS*NN];      // (hl_r, hl_i, c_r, c_i)  64 MB
__device__ float2 g_hin[BG*NSUB*NN];   // subchunk input states    1 MB

// ---------------- f32x2 helpers ----------------
__device__ __forceinline__ ull pk(float x, float y) {
    ull r; asm("mov.b64 %0, {%1, %2};" : "=l"(r) : "f"(x), "f"(y)); return r;
}
__device__ __forceinline__ void fma2(ull& d, ull a, ull b) {
    asm("fma.rn.f32x2 %0, %1, %2, %0;" : "+l"(d) : "l"(a), "l"(b));
}
__device__ __forceinline__ ull neg2(ull v) { return v ^ 0x8000000080000000ULL; }
__device__ __forceinline__ float comp(ull v, int e) {
    float x, y;
    asm("mov.b64 {%0, %1}, %2;" : "=f"(x), "=f"(y) : "l"(v));
    return e ? y : x;
}
__device__ __forceinline__ float warpsum(float v) {
    #pragma unroll
    for (int off = 16; off; off >>= 1) v += __shfl_xor_sync(0xffffffffu, v, off);
    return v;
}
__device__ __forceinline__ float clampdt(float v) {
    return fminf(fmaxf(v, 1e-4f), 2.0f);
}

// ---------------------------------------------------------------------------
// Kernel 1 (fused with local scan): each warp owns one (bg, subchunk) slice
// of 32 consecutive tokens. Per pass of 4 tokens: FFMA2 B-projection, dt via
// warp reduction, then in-register complex scan; writes (h_local, c) to g_hc.
// ---------------------------------------------------------------------------
__global__ __launch_bounds__(256, 2) void k1_scan(
    const float* __restrict__ xr_g, const float* __restrict__ xi_g,
    const float* __restrict__ logA, const float* __restrict__ Aph_g,
    const float* __restrict__ Bwr,  const float* __restrict__ Bwi,
    const float* __restrict__ dtw_g, const float* __restrict__ dtb_g)
{
    extern __shared__ float sm[];
    float* swr = sm;                       // [d][n] 8192 floats (32 KB)
    float* swi = swr + 8192;               // 32 KB
    float* dtw = swi + 8192;               // 512
    float* nlA = dtw + 512;                // 512
    float* aph = nlA + 512;                // 512
    float2* xbase = (float2*)(aph + 512);  // 8 warps * 512 float2 (32 KB)

    const int tid = threadIdx.x;
    for (int i = tid; i < 8192; i += 256) {
        int d = i & 127, n = i >> 7;
        swr[d*64 + n] = Bwr[n*128 + d];
        swi[d*64 + n] = Bwi[n*128 + d];
    }
    for (int i = tid; i < 512; i += 256) {
        dtw[i] = dtw_g[i];
        nlA[i] = -log1pf(expf(logA[i]));   // -softplus
        aph[i] = Aph_g[i];
    }
    __syncthreads();

    const int w = tid >> 5, l = tid & 31;
    const int slice = blockIdx.x*8 + w;
    if (slice >= BG*NSUB) return;
    const int bg = slice >> 6, sub = slice & 63;
    const int b = bg >> 3, g = bg & 7;
    float2* xpr = xbase + w*512;           // [2 pairs][128 d] token-pair f32x2
    float2* xpi = xpr + 256;
    const float db0 = dtb_g[0], db1 = dtb_g[1];

    float hr[2] = {0.f, 0.f}, hi[2] = {0.f, 0.f};
    float cr[2] = {1.f, 1.f}, ci[2] = {0.f, 0.f};

    for (int pass = 0; pass < 8; ++pass) {
        const int s0 = sub*SUB + pass*4;
        const int t0 = (b*SS + s0)*GG + g;     // tokens stride GG in memory

        // ---- stage x token-pair interleaved ----
        #pragma unroll
        for (int p = 0; p < 2; ++p) {
            int ta = t0 + 2*p*GG, tb = ta + GG;
            float4 r0 = ((const float4*)(xr_g + (size_t)ta*DD))[l];
            float4 r1 = ((const float4*)(xr_g + (size_t)tb*DD))[l];
            float4 i0 = ((const float4*)(xi_g + (size_t)ta*DD))[l];
            float4 i1 = ((const float4*)(xi_g + (size_t)tb*DD))[l];
            float2* xp = xpr + p*128;
            *(float4*)&xp[4*l]     = make_float4(r0.x, r1.x, r0.y, r1.y);
            *(float4*)&xp[4*l + 2] = make_float4(r0.z, r1.z, r0.w, r1.w);
            float2* xq = xpi + p*128;
            *(float4*)&xq[4*l]     = make_float4(i0.x, i1.x, i0.y, i1.y);
            *(float4*)&xq[4*l + 2] = make_float4(i0.z, i1.z, i0.w, i1.w);
        }
        __syncwarp();

        // ---- dt logits ----
        float dm[4], dp[4];
        #pragma unroll
        for (int p = 0; p < 2; ++p) {
            float a0x=0.f, a0y=0.f, a1x=0.f, a1y=0.f;
            #pragma unroll
            for (int k = 0; k < 4; ++k) {
                int d = l + 32*k;
                float2 xr = xpr[p*128 + d];
                float2 xi = xpi[p*128 + d];
                float w0r = dtw[d], w0i = dtw[128 + d];
                float w1r = dtw[256 + d], w1i = dtw[384 + d];
                a0x = fmaf(xr.x, w0r, fmaf(xi.x, w0i, a0x));
                a0y = fmaf(xr.y, w0r, fmaf(xi.y, w0i, a0y));
                a1x = fmaf(xr.x, w1r, fmaf(xi.x, w1i, a1x));
                a1y = fmaf(xr.y, w1r, fmaf(xi.y, w1i, a1y));
            }
            a0x = warpsum(a0x); a0y = warpsum(a0y);
            a1x = warpsum(a1x); a1y = warpsum(a1y);
            dm[2*p]   = clampdt(__expf(a0x + db0));
            dm[2*p+1] = clampdt(__expf(a0y + db0));
            dp[2*p]   = clampdt(__expf(a1x + db1));
            dp[2*p+1] = clampdt(__expf(a1y + db1));
        }

        // ---- FFMA2 complex B projection (4 tokens as 2 f32x2 pairs) ----
        ull aR[2][2], aI[2][2];
        #pragma unroll
        for (int p = 0; p < 2; ++p) { aR[p][0]=0; aR[p][1]=0; aI[p][0]=0; aI[p][1]=0; }

        #pragma unroll 4
        for (int d = 0; d < 128; d += 2) {
            float r0a = swr[d*64 + l],      r1a = swr[d*64 + l + 32];
            float r0b = swr[d*64 + 64 + l], r1b = swr[d*64 + 96 + l];
            float i0a = swi[d*64 + l],      i1a = swi[d*64 + l + 32];
            float i0b = swi[d*64 + 64 + l], i1b = swi[d*64 + 96 + l];
            ull wr0a = pk(r0a, r0a), wr1a = pk(r1a, r1a);
            ull wr0b = pk(r0b, r0b), wr1b = pk(r1b, r1b);
            ull wi0a = pk(i0a, i0a), wi1a = pk(i1a, i1a);
            ull wi0b = pk(i0b, i0b), wi1b = pk(i1b, i1b);
            ull ni0a = neg2(wi0a), ni1a = neg2(wi1a);
            ull ni0b = neg2(wi0b), ni1b = neg2(wi1b);
            #pragma unroll
            for (int p = 0; p < 2; ++p) {
                float4 xr4 = *(const float4*)(xpr + p*128 + d);
                float4 xi4 = *(const float4*)(xpi + p*128 + d);
                ull xra = pk(xr4.x, xr4.y), xrb = pk(xr4.z, xr4.w);
                ull xia = pk(xi4.x, xi4.y), xib = pk(xi4.z, xi4.w);
                fma2(aR[p][0], xra, wr0a); fma2(aR[p][0], xia, ni0a);
                fma2(aI[p][0], xra, wi0a); fma2(aI[p][0], xia, wr0a);
                fma2(aR[p][1], xra, wr1a); fma2(aR[p][1], xia, ni1a);
                fma2(aI[p][1], xra, wi1a); fma2(aI[p][1], xia, wr1a);
                fma2(aR[p][0], xrb, wr0b); fma2(aR[p][0], xib, ni0b);
                fma2(aI[p][0], xrb, wi0b); fma2(aI[p][0], xib, wr0b);
                fma2(aR[p][1], xrb, wr1b); fma2(aR[p][1], xib, ni1b);
                fma2(aI[p][1], xrb, wi1b); fma2(aI[p][1], xib, wr1b);
            }
        }

        // ---- in-register local scan + store (h_local, cumprod) ----
        #pragma unroll
        for (int j = 0; j < 4; ++j) {
            const int p = j >> 1, e = j & 1;
            const int s = s0 + j;
            const float dmv = dm[j], dpv = dp[j];
            const size_t idx = ((size_t)bg*SS + s)*NN;
            #pragma unroll
            for (int ns = 0; ns < 2; ++ns) {
                int n = l + 32*ns;
                float am = __expf(dmv * nlA[g*64 + n]);
                float sn, cs;
                __sincosf(dpv * aph[g*64 + n], &sn, &cs);
                float ar = am*cs, ai = am*sn;
                float br = comp(aR[p][ns], e) * dmv;
                float bi = comp(aI[p][ns], e) * dmv;
                float nhr = fmaf(ar, hr[ns], fmaf(-ai, hi[ns], br));
                float nhi = fmaf(ar, hi[ns], fmaf( ai, hr[ns], bi));
                float ncr = ar*cr[ns] - ai*ci[ns];
                float nci = ar*ci[ns] + ai*cr[ns];
                hr[ns] = nhr; hi[ns] = nhi; cr[ns] = ncr; ci[ns] = nci;
                g_hc[idx + n] = make_float4(nhr, nhi, ncr, nci);
            }
        }
        __syncwarp();
    }
}

// ---------------------------------------------------------------------------
// Kernel 2b: sequential subchunk combine; renorm every 8th subchunk boundary.
// ---------------------------------------------------------------------------
__global__ __launch_bounds__(64) void k2b_combine(void)
{
    int bg = blockIdx.x;
    int n = threadIdx.x;
    float hr = 0.f, hi = 0.f;

    float4 ebuf[8];
    #pragma unroll
    for (int j = 0; j < 8; ++j)
        ebuf[j] = g_hc[((size_t)bg*SS + j*SUB + 31)*NN + n];

    for (int s0 = 0; s0 < NSUB; s0 += 8) {
        #pragma unroll
        for (int j = 0; j < 8; ++j) {
            float4 e = ebuf[j];
            int nsub = s0 + 8 + j;
            if (nsub < NSUB)
                ebuf[j] = g_hc[((size_t)bg*SS + nsub*SUB + 31)*NN + n];
            int sub = s0 + j;
            g_hin[(bg*NSUB + sub)*NN + n] = make_float2(hr, hi);
            float nr = fmaf(e.z, hr, fmaf(-e.w, hi, e.x));
            float ni = fmaf(e.z, hi, fmaf( e.w, hr, e.y));
            if ((sub & 7) == 7) {
                float nm = sqrtf(nr*nr + ni*ni + 1e-8f);
                float sc = fminf(nm, 100.0f)/nm;
                nr *= sc; ni *= sc;
            }
            hr = nr; hi = ni;
        }
    }
}

// ---------------------------------------------------------------------------
// Kernel 3: correction h = h_local + c*h_in (+renorm at s%256==255) fused with
// complex C projection, FFMA2 token-pair packed. 2 CTAs/SM, persistent.
// ---------------------------------------------------------------------------
__global__ __launch_bounds__(256, 2) void k3_out(
    const float* __restrict__ Cwr, const float* __restrict__ Cwi,
    float* __restrict__ out)
{
    extern __shared__ float sm[];
    float* crr = sm;                 // [n][d] 8192 floats (32 KB)
    float* cii = crr + 8192;         // 32 KB
    float* hbase = cii + 8192;       // 8 warps * 768 floats (24 KB)

    const int tid = threadIdx.x;
    for (int i = tid; i < 8192; i += 256) {
        int d = i & 127, n = i >> 7;
        crr[n*128 + d] = Cwr[d*64 + n];
        cii[n*128 + d] = Cwi[d*64 + n];
    }
    __syncthreads();

    const int w = tid >> 5, l = tid & 31;
    float* hrp = hbase + w*768;      // [2 pairs][64 n][2 parity]
    float* hip = hrp + 256;
    float* hnp = hip + 256;
    const size_t OFF = (size_t)NTOK*DD;

    for (int grp = blockIdx.x; grp < NTOK/32; grp += gridDim.x) {
        const int tbase = grp*32 + w*4;

        // ---- stage corrected h ----
        #pragma unroll
        for (int k = 0; k < 4; ++k) {
            int t = tbase + k;
            int b = t >> 14, g = t & 7, s = (t >> 3) & 2047;
            int bg = b*GG + g;
            size_t idx = ((size_t)bg*SS + s)*NN;
            int hini = (bg*NSUB + (s >> 5))*NN;
            int p = k >> 1, e = k & 1;
            #pragma unroll
            for (int ns = 0; ns < 2; ++ns) {
                int n = l + 32*ns;
                float4 hc = g_hc[idx + n];
                float2 hin = g_hin[hini + n];
                float hrv = fmaf(hc.z, hin.x, fmaf(-hc.w, hin.y, hc.x));
                float hiv = fmaf(hc.z, hin.y, fmaf( hc.w, hin.x, hc.y));
                if ((s & 255) == 255) {
                    float nm = sqrtf(hrv*hrv + hiv*hiv + 1e-8f);
                    float sc = fminf(nm, 100.0f)/nm;
                    hrv *= sc; hiv *= sc;
                }
                hrp[(p*64 + n)*2 + e] = hrv;
                hip[(p*64 + n)*2 + e] = hiv;
                hnp[(p*64 + n)*2 + e] = -hiv;
            }
        }
        __syncwarp();

        // ---- FFMA2 C projection: lane owns d = {2l,2l+1,2l+64,2l+65} ----
        ull aR[4][2], aI[4][2];
        #pragma unroll
        for (int i = 0; i < 4; ++i) { aR[i][0]=0; aR[i][1]=0; aI[i][0]=0; aI[i][1]=0; }

        #pragma unroll 2
        for (int n = 0; n < NN; ++n) {
            float2 w0 = *(const float2*)&crr[n*128 + 2*l];
            float2 w1 = *(const float2*)&crr[n*128 + 2*l + 64];
            float2 v0 = *(const float2*)&cii[n*128 + 2*l];
            float2 v1 = *(const float2*)&cii[n*128 + 2*l + 64];
            ull cr0 = pk(w0.x, w0.x), cr1 = pk(w0.y, w0.y);
            ull cr2 = pk(w1.x, w1.x), cr3 = pk(w1.y, w1.y);
            ull ci0 = pk(v0.x, v0.x), ci1 = pk(v0.y, v0.y);
            ull ci2 = pk(v1.x, v1.x), ci3 = pk(v1.y, v1.y);
            #pragma unroll
            for (int p = 0; p < 2; ++p) {
                ull hr = *(const ull*)&hrp[(p*64 + n)*2];
                ull hi = *(const ull*)&hip[(p*64 + n)*2];
                ull hn = *(const ull*)&hnp[(p*64 + n)*2];
                fma2(aR[0][p], hr, cr0); fma2(aR[0][p], hn, ci0);
                fma2(aI[0][p], hr, ci0); fma2(aI[0][p], hi, cr0);
                fma2(aR[1][p], hr, cr1); fma2(aR[1][p], hn, ci1);
                fma2(aI[1][p], hr, ci1); fma2(aI[1][p], hi, cr1);
                fma2(aR[2][p], hr, cr2); fma2(aR[2][p], hn, ci2);
                fma2(aI[2][p], hr, ci2); fma2(aI[2][p], hi, cr2);
                fma2(aR[3][p], hr, cr3); fma2(aR[3][p], hn, ci3);
                fma2(aI[3][p], hr, ci3); fma2(aI[3][p], hi, cr3);
            }
        }

        // ---- output ----
        #pragma unroll
        for (int k = 0; k < 4; ++k) {
            int t = tbase + k;
            int p = k >> 1, e = k & 1;
            float r0 = comp(aR[0][p], e), r1 = comp(aR[1][p], e);
            float r2 = comp(aR[2][p], e), r3 = comp(aR[3][p], e);
            float i0 = comp(aI[0][p], e), i1 = comp(aI[1][p], e);
            float i2 = comp(aI[2][p], e), i3 = comp(aI[3][p], e);
            *(float2*)&out[(size_t)t*DD + 2*l]            = make_float2(r0, r1);
            *(float2*)&out[(size_t)t*DD + 2*l + 64]       = make_float2(r2, r3);
            *(float2*)&out[OFF + (size_t)t*DD + 2*l]      = make_float2(i0, i1);
            *(float2*)&out[OFF + (size_t)t*DD + 2*l + 64] = make_float2(i2, i3);
        }
        __syncwarp();
    }
}

// ---------------------------------------------------------------------------
extern "C" void kernel_launch(void* const* d_in, const int* in_sizes, int n_in,
                              void* d_out, int out_size)
{
    const float* x_r  = (const float*)d_in[0];
    const float* x_i  = (const float*)d_in[1];
    const float* logA = (const float*)d_in[2];
    const float* Aph  = (const float*)d_in[3];
    const float* Bwr  = (const float*)d_in[4];
    const float* Bwi  = (const float*)d_in[5];
    const float* Cwr  = (const float*)d_in[6];
    const float* Cwi  = (const float*)d_in[7];
    const float* dtw  = (const float*)d_in[8];
    const float* dtb  = (const float*)d_in[9];
    float* out = (float*)d_out;

    const int smem1 = (8192*2 + 512*3 + 8*1024) * 4;   // 104448 B
    const int smem3 = (8192*2 + 8*768) * 4;            // 90112 B
    cudaFuncSetAttribute(k1_scan, cudaFuncAttributeMaxDynamicSharedMemorySize, smem1);
    cudaFuncSetAttribute(k3_out,  cudaFuncAttributeMaxDynamicSharedMemorySize, smem3);

    k1_scan<<<(BG*NSUB)/8, 256, smem1>>>(x_r, x_i, logA, Aph, Bwr, Bwi, dtw, dtb);
    k2b_combine<<<BG, 64>>>();
    k3_out<<<296, 256, smem3>>>(Cwr, Cwi, out);
}